// round 12
// baseline (speedup 1.0000x reference)
#include <cuda_runtime.h>
#include <cstddef>

typedef unsigned long long u64;

#define DIM   16384
#define OUT_N 1000
#define BLK   256

// phys = a ^ (bits 9-12 folded into bank bits 1-4); bit 0 preserved (float2-safe)
__device__ __forceinline__ unsigned swz(unsigned a){ return a ^ (((a>>9)&15u)<<1); }

__device__ __forceinline__ u64 pk2(float lo, float hi){ u64 r; asm("mov.b64 %0,{%1,%2};":"=l"(r):"f"(lo),"f"(hi)); return r; }
__device__ __forceinline__ u64 dup2(float x){ return pk2(x,x); }
__device__ __forceinline__ void unpk2(u64 v, float& lo, float& hi){ asm("mov.b64 {%0,%1},%2;":"=f"(lo),"=f"(hi):"l"(v)); }
__device__ __forceinline__ u64 fma2(u64 a,u64 b,u64 c){ u64 d; asm("fma.rn.f32x2 %0,%1,%2,%3;":"=l"(d):"l"(a),"l"(b),"l"(c)); return d; }
__device__ __forceinline__ u64 mul2(u64 a,u64 b){ u64 d; asm("mul.rn.f32x2 %0,%1,%2;":"=l"(d):"l"(a),"l"(b)); return d; }

// y0 = c*x0 - s*x1 ; y1 = s*x0 + c*x1     (needs cc,ss,ns={-s})
__device__ __forceinline__ void ry2(u64&x0,u64&x1,u64 cc,u64 ss,u64 ns){
    u64 y0 = fma2(cc,x0, mul2(ns,x1));
    u64 y1 = fma2(ss,x0, mul2(cc,x1));
    x0=y0; x1=y1;
}
// CZ folded (x1 logically pre-negated): y0 = c*x0 + s*x1 ; y1 = s*x0 - c*x1
__device__ __forceinline__ void ry2cz(u64&x0,u64&x1,u64 cc,u64 ss,u64 nc){
    u64 y0 = fma2(cc,x0, mul2(ss,x1));
    u64 y1 = fma2(ss,x0, mul2(nc,x1));
    x0=y0; x1=y1;
}

// Fused CZ + RY(high PH) + RY(low PL) on 16 packed (f32x2) amps; g = smem row {cc0,ss0,ns0,nc0,cc1,ss1,ns1}
template<int PH,int PL>
__device__ __forceinline__ void gate2(u64 q[16], const u64* __restrict__ g){
    const u64 cc0=g[0],ss0=g[1],ns0=g[2],nc0=g[3],cc1=g[4],ss1=g[5],ns1=g[6];
#pragma unroll
    for(int k=0;k<16;++k) if(!((k>>PH)&1) && !((k>>PL)&1)){
        const int k01=k|(1<<PL), k10=k|(1<<PH), k11=k10|(1<<PL);
        ry2  (q[k],  q[k10], cc0,ss0,ns0);   // (a00,a10)
        ry2cz(q[k01],q[k11], cc0,ss0,nc0);   // (a01,a11) with CZ sign fold
        ry2  (q[k],  q[k01], cc1,ss1,ns1);
        ry2  (q[k10],q[k11], cc1,ss1,ns1);
    }
}
template<int P>
__device__ __forceinline__ void bias2(u64 q[16], const u64* __restrict__ b){
    const u64 cc=b[0],ss=b[1],ns=b[2];
#pragma unroll
    for(int k=0;k<16;++k) if(!((k>>P)&1)) ry2(q[k], q[k|(1<<P)], cc,ss,ns);
}

// 64-bit tile ld/st, spectator = amp bit 0. swz linear => per-k offsets compile-time.
template<int B3,int B2,int B1,int B0>
__device__ __forceinline__ void ld64(const float* __restrict__ S, unsigned pb, u64 q[16]){
#pragma unroll
    for(int k=0;k<16;++k){
        const unsigned off = swz((unsigned)((((k>>3)&1)<<B3)|(((k>>2)&1)<<B2)|(((k>>1)&1)<<B1)|((k&1)<<B0)));
        q[k] = *(const u64*)(S + (pb ^ off));
    }
}
template<int B3,int B2,int B1,int B0>
__device__ __forceinline__ void st64(float* __restrict__ S, unsigned pb, const u64 q[16]){
#pragma unroll
    for(int k=0;k<16;++k){
        const unsigned off = swz((unsigned)((((k>>3)&1)<<B3)|(((k>>2)&1)<<B2)|(((k>>1)&1)<<B1)|((k&1)<<B0)));
        *(u64*)(S + (pb ^ off)) = q[k];
    }
}

__global__ __launch_bounds__(BLK, 3)
void qnn_kernel(const float* __restrict__ input,
                const float* __restrict__ weights,   // (2,13,2)
                const float* __restrict__ bias,      // (14,)
                float* __restrict__ out)             // (B,1000)
{
    extern __shared__ float S[];                     // DIM floats, swizzled
    __shared__ u64 Gp[26][7];                        // packed {cc0,ss0,ns0,nc0,cc1,ss1,ns1}
    __shared__ u64 Bp[14][3];                        // packed bias {cc,ss,ns} by BIT position
    __shared__ float warpsum[BLK/32];
    __shared__ float s_inv;

    const int tid = threadIdx.x;
    const int b   = blockIdx.x;

    // ---- packed gate constants ----
    if (tid < 26) {
        int l, i;
        if (tid < 7)       { l=0; i=2*tid; }
        else if (tid < 13) { l=0; i=2*(tid-7)+1; }
        else if (tid < 20) { l=1; i=2*(tid-13); }
        else               { l=1; i=2*(tid-20)+1; }
        float c0,s0,c1,s1;
        sincosf(0.5f*weights[l*26+i*2+0], &s0, &c0);
        sincosf(0.5f*weights[l*26+i*2+1], &s1, &c1);
        Gp[tid][0]=dup2(c0); Gp[tid][1]=dup2(s0); Gp[tid][2]=dup2(-s0); Gp[tid][3]=dup2(-c0);
        Gp[tid][4]=dup2(c1); Gp[tid][5]=dup2(s1); Gp[tid][6]=dup2(-s1);
    }
    if (tid < 14) {                                  // bit w holds qubit 13-w
        float c,s; sincosf(0.5f*bias[13-tid], &s, &c);
        Bp[tid][0]=dup2(c); Bp[tid][1]=dup2(s); Bp[tid][2]=dup2(-s);
    }
    __syncthreads();

    u64 q[16];
    u64 acc2 = 0;                                    // {0.f,0.f}

    // ===== S1 (gmem -> regs -> smem): tile(13,12,11,10), spec 0
    //        bias13..10 + E1(13,12) + E1(11,10) + O1(12,11) + E2(13,12)
    const float* row = input + (size_t)b * DIM;
#pragma unroll 1
    for (int it=0; it<2; ++it){
        const unsigned base = ((unsigned)tid<<1) | ((unsigned)it<<9);
#pragma unroll
        for (int k=0;k<16;++k){
            q[k] = *(const u64*)(row + (base | ((unsigned)k<<10)));
            acc2 = fma2(q[k], q[k], acc2);
        }
        bias2<3>(q,Bp[13]); bias2<2>(q,Bp[12]); bias2<1>(q,Bp[11]); bias2<0>(q,Bp[10]);
        gate2<3,2>(q,Gp[0]); gate2<1,0>(q,Gp[1]); gate2<2,1>(q,Gp[7]); gate2<3,2>(q,Gp[13]);
        st64<13,12,11,10>(S, swz(base), q);
    }
    // norm reduction (deferred; consumed only in epilogue)
    {
        float a0,a1; unpk2(acc2,a0,a1);
        float acc = a0+a1;
#pragma unroll
        for (int o=16;o;o>>=1) acc += __shfl_xor_sync(~0u, acc, o);
        if ((tid&31)==0) warpsum[tid>>5] = acc;
    }
    __syncthreads();
    if (tid < BLK/32){
        float v = warpsum[tid];
#pragma unroll
        for (int o=(BLK/32)/2;o;o>>=1) v += __shfl_xor_sync(0xffu, v, o);
        if (!tid) s_inv = 1.f/v;
    }

    // ===== S2: tile(9,8,7,6): bias9..6, E1(9,8), E1(7,6), O1(8,7)
#pragma unroll 1
    for (int it=0; it<2; ++it){
        const unsigned base = (((unsigned)tid&31u)<<1) | ((((unsigned)tid>>5)&7u)<<10) | ((unsigned)it<<13);
        const unsigned pb = swz(base);
        ld64<9,8,7,6>(S, pb, q);
        bias2<3>(q,Bp[9]); bias2<2>(q,Bp[8]); bias2<1>(q,Bp[7]); bias2<0>(q,Bp[6]);
        gate2<3,2>(q,Gp[2]); gate2<1,0>(q,Gp[3]); gate2<2,1>(q,Gp[9]);
        st64<9,8,7,6>(S, pb, q);
    }
    __syncthreads();

    // ===== S3: tile(5,4,3,2): bias5..2, E1(5,4), E1(3,2), O1(4,3)
#pragma unroll 1
    for (int it=0; it<2; ++it){
        const unsigned base = (((unsigned)tid&1u)<<1) | ((((unsigned)tid>>1)&7u)<<10)
                            | ((((unsigned)tid>>4)&15u)<<6) | ((unsigned)it<<13);
        const unsigned pb = swz(base);
        ld64<5,4,3,2>(S, pb, q);
        bias2<3>(q,Bp[5]); bias2<2>(q,Bp[4]); bias2<1>(q,Bp[3]); bias2<0>(q,Bp[2]);
        gate2<3,2>(q,Gp[4]); gate2<1,0>(q,Gp[5]); gate2<2,1>(q,Gp[11]);
        st64<5,4,3,2>(S, pb, q);
    }
    __syncthreads();

    // ===== S4: tile(3,2,1,0), spectator bit 4 (two 32-bit accesses, clean 2-way)
    //        bias1,0, E1(1,0), O1(2,1), E2(1,0)
#pragma unroll 1
    for (int it=0; it<2; ++it){
        const unsigned base = (((unsigned)tid&15u)<<9) | ((((unsigned)tid>>4)&15u)<<5) | ((unsigned)it<<13);
        const unsigned pb = swz(base);
#pragma unroll
        for (int k=0;k<16;++k){
            const unsigned p0 = pb ^ swz((unsigned)k);
            q[k] = pk2(S[p0], S[p0 ^ 16u]);
        }
        bias2<1>(q,Bp[1]); bias2<0>(q,Bp[0]);
        gate2<1,0>(q,Gp[6]); gate2<2,1>(q,Gp[12]); gate2<1,0>(q,Gp[19]);
#pragma unroll
        for (int k=0;k<16;++k){
            const unsigned p0 = pb ^ swz((unsigned)k);
            float lo,hi; unpk2(q[k],lo,hi);
            S[p0] = lo; S[p0 ^ 16u] = hi;
        }
    }
    __syncthreads();

    // ===== S5: tile(11,10,9,8): O1(10,9), E2(11,10), E2(9,8), O2(10,9)
#pragma unroll 1
    for (int it=0; it<2; ++it){
        const unsigned base = (((unsigned)tid&127u)<<1) | ((((unsigned)tid>>7)&1u)<<12) | ((unsigned)it<<13);
        const unsigned pb = swz(base);
        ld64<11,10,9,8>(S, pb, q);
        gate2<2,1>(q,Gp[8]); gate2<3,2>(q,Gp[14]); gate2<1,0>(q,Gp[15]); gate2<2,1>(q,Gp[21]);
        st64<11,10,9,8>(S, pb, q);
    }
    __syncthreads();

    // ===== S6: tile(12,11,6,5): O1(6,5), O2(12,11)
#pragma unroll 1
    for (int it=0; it<2; ++it){
        const unsigned base = (((unsigned)tid&15u)<<1) | ((((unsigned)tid>>4)&7u)<<7)
                            | ((((unsigned)tid>>7)&1u)<<10) | ((unsigned)it<<13);
        const unsigned pb = swz(base);
        ld64<12,11,6,5>(S, pb, q);
        gate2<1,0>(q,Gp[10]); gate2<3,2>(q,Gp[20]);
        st64<12,11,6,5>(S, pb, q);
    }
    __syncthreads();

    // ===== S7: tile(8,7,6,5): E2(7,6), O2(8,7)
#pragma unroll 1
    for (int it=0; it<2; ++it){
        const unsigned base = (((unsigned)tid&15u)<<1) | ((((unsigned)tid>>4)&15u)<<9) | ((unsigned)it<<13);
        const unsigned pb = swz(base);
        ld64<8,7,6,5>(S, pb, q);
        gate2<2,1>(q,Gp[16]); gate2<3,2>(q,Gp[22]);
        st64<8,7,6,5>(S, pb, q);
    }
    __syncthreads();

    // ===== S8: tile(5,4,3,2): E2(5,4), E2(3,2), O2(4,3)
#pragma unroll 1
    for (int it=0; it<2; ++it){
        const unsigned base = (((unsigned)tid&1u)<<1) | ((((unsigned)tid>>1)&7u)<<10)
                            | ((((unsigned)tid>>4)&15u)<<6) | ((unsigned)it<<13);
        const unsigned pb = swz(base);
        ld64<5,4,3,2>(S, pb, q);
        gate2<3,2>(q,Gp[17]); gate2<1,0>(q,Gp[18]); gate2<2,1>(q,Gp[24]);
        st64<5,4,3,2>(S, pb, q);
    }
    __syncthreads();

    // ===== S9: tile(6,5,2,1): O2(6,5), O2(2,1)
#pragma unroll 1
    for (int it=0; it<2; ++it){
        const unsigned base = (((unsigned)tid&3u)<<9) | ((((unsigned)tid>>2)&3u)<<3)
                            | ((((unsigned)tid>>4)&3u)<<7) | ((((unsigned)tid>>6)&3u)<<11)
                            | ((unsigned)it<<13);
        const unsigned pb = swz(base);
        ld64<6,5,2,1>(S, pb, q);
        gate2<3,2>(q,Gp[23]); gate2<1,0>(q,Gp[25]);
        st64<6,5,2,1>(S, pb, q);
    }
    __syncthreads();

    // ---- epilogue: probs of last OUT_N states, scaled by 1/||x||^2 ----
    const float inv = s_inv;
    float* orow = out + (size_t)b*OUT_N;
    for (int j=tid; j<OUT_N; j+=BLK){
        float a = S[swz((unsigned)(DIM-OUT_N+j))];
        orow[j] = a*a*inv;
    }
}

extern "C" void kernel_launch(void* const* d_in, const int* in_sizes, int n_in,
                              void* d_out, int out_size)
{
    const float* input   = (const float*)d_in[0];   // (B,16384) f32
    const float* weights = (const float*)d_in[1];   // (2,13,2)  f32
    const float* bias    = (const float*)d_in[2];   // (14,)     f32
    float* out = (float*)d_out;                     // (B,1000)  f32

    const int B = in_sizes[0] / DIM;                // 512

    cudaFuncSetAttribute(qnn_kernel,
                         cudaFuncAttributeMaxDynamicSharedMemorySize,
                         DIM * (int)sizeof(float));

    qnn_kernel<<<B, BLK, DIM * sizeof(float)>>>(input, weights, bias, out);
}

// round 13
// speedup vs baseline: 2.0717x; 2.0717x over previous
#include <cuda_runtime.h>
#include <cstddef>

#define DIM   16384
#define OUT_N 1000
#define BLK   256

// bank bits 2-4 ^= addr bits 10-12; bits 0,1 intact (float4-safe). Linear over GF(2).
__device__ __forceinline__ unsigned swz(unsigned a){ return a ^ (((a>>10)&7u)<<2); }

// Tangent-form fused CZ + RY(high PH) + RY(low PL); g = (t0, t1). Scale c0*c1 deferred.
template<int PH,int PL>
__device__ __forceinline__ void gate2(float r[16], float2 g){
    const float t0 = g.x, t1 = g.y;
#pragma unroll
    for(int k=0;k<16;++k) if(!((k>>PH)&1) && !((k>>PL)&1)){
        const int k01=k|(1<<PL), k10=k|(1<<PH), k11=k10|(1<<PL);
        float y00 = fmaf(-t0, r[k10],  r[k]);
        float y10 = fmaf( t0, r[k],    r[k10]);
        float y01 = fmaf( t0, r[k11],  r[k01]);   // a01 - t0*(-a11)  (CZ fold)
        float y11 = fmaf( t0, r[k01], -r[k11]);   // -a11 + t0*a01
        r[k]   = fmaf(-t1, y01, y00);
        r[k01] = fmaf( t1, y00, y01);
        r[k10] = fmaf(-t1, y11, y10);
        r[k11] = fmaf( t1, y10, y11);
    }
}
template<int P>
__device__ __forceinline__ void bias1(float r[16], float t){
#pragma unroll
    for(int k=0;k<16;++k) if(!((k>>P)&1)){
        const int k1 = k|(1<<P);
        float y0 = fmaf(-t, r[k1], r[k]);
        r[k1]    = fmaf( t, r[k],  r[k1]);
        r[k]     = y0;
    }
}

template<int B3,int B2,int B1,int B0>
__device__ __forceinline__ void ldtile(const float* __restrict__ S, unsigned pb, float r[16]){
#pragma unroll
    for(int k=0;k<16;++k){
        const unsigned off = swz((unsigned)((((k>>3)&1)<<B3)|(((k>>2)&1)<<B2)|(((k>>1)&1)<<B1)|((k&1)<<B0)));
        r[k] = S[pb ^ off];
    }
}
template<int B3,int B2,int B1,int B0>
__device__ __forceinline__ void sttile(float* __restrict__ S, unsigned pb, const float r[16]){
#pragma unroll
    for(int k=0;k<16;++k){
        const unsigned off = swz((unsigned)((((k>>3)&1)<<B3)|(((k>>2)&1)<<B2)|(((k>>1)&1)<<B1)|((k&1)<<B0)));
        S[pb ^ off] = r[k];
    }
}

__global__ __launch_bounds__(BLK, 3)
void qnn_kernel(const float* __restrict__ input,
                const float* __restrict__ weights,   // (2,13,2)
                const float* __restrict__ bias,      // (14,)
                float* __restrict__ out)             // (B,1000)
{
    extern __shared__ float S[];                     // DIM floats, swizzled layout
    __shared__ float2 Gt[26];                        // (t0,t1) per fused gate
    __shared__ float  Bt[14];                        // bias tan, by BIT position
    __shared__ float  Cg[26], Cb[14];                // deferred cosine factors
    __shared__ float  warpsum[BLK/32];
    __shared__ float  s_inv;

    const int tid = threadIdx.x;
    const int b   = blockIdx.x;

    if (tid < 26) {
        int l, i;
        if (tid < 7)       { l=0; i=2*tid; }
        else if (tid < 13) { l=0; i=2*(tid-7)+1; }
        else if (tid < 20) { l=1; i=2*(tid-13); }
        else               { l=1; i=2*(tid-20)+1; }
        float c0,s0,c1,s1;
        sincosf(0.5f*weights[l*26+i*2+0], &s0, &c0);
        sincosf(0.5f*weights[l*26+i*2+1], &s1, &c1);
        Gt[tid] = make_float2(s0/c0, s1/c1);
        Cg[tid] = c0*c1;
    }
    if (tid < 14) {                                  // bit w holds qubit 13-w
        float c,s; sincosf(0.5f*bias[13-tid], &s, &c);
        Bt[tid] = s/c; Cb[tid] = c;
    }
    __syncthreads();

    // warp 0: product of all 66 cosines (5-level tree)
    float scl = 1.f;
    if (tid < 32) {
        if (tid < 26) scl *= Cg[tid];
        if (tid < 14) scl *= Cb[tid];
#pragma unroll
        for (int o=16;o;o>>=1) scl *= __shfl_xor_sync(~0u, scl, o);
    }

    float r[16];
    float acc0 = 0.f, acc1 = 0.f;

    // ===== S1 (gmem -> regs -> smem): tile(13,12,11,10)
    //   bias13..10, E1(13,12), E1(11,10), O1(12,11), E2(13,12)
    const float* row = input + (size_t)b * DIM;
#pragma unroll 1
    for (int it=0; it<4; ++it){
        const unsigned idx = (unsigned)tid | ((unsigned)it<<8);   // [0,1024)
#pragma unroll
        for (int k=0;k<16;++k){
            float v = row[idx | ((unsigned)k<<10)];
            if (k & 1) acc1 = fmaf(v,v,acc1); else acc0 = fmaf(v,v,acc0);
            r[k] = v;
        }
        bias1<3>(r,Bt[13]); bias1<2>(r,Bt[12]); bias1<1>(r,Bt[11]); bias1<0>(r,Bt[10]);
        gate2<3,2>(r,Gt[0]); gate2<1,0>(r,Gt[1]); gate2<2,1>(r,Gt[7]); gate2<3,2>(r,Gt[13]);
        sttile<13,12,11,10>(S, swz(idx), r);
    }
    {
        float acc = acc0 + acc1;
#pragma unroll
        for (int o=16;o;o>>=1) acc += __shfl_xor_sync(~0u, acc, o);
        if ((tid&31)==0) warpsum[tid>>5] = acc;
    }
    __syncthreads();                                 // orders S1 stores before S2 loads
    if (tid < BLK/32){
        float v = warpsum[tid];
#pragma unroll
        for (int o=(BLK/32)/2;o;o>>=1) v += __shfl_xor_sync(0xffu, v, o);
        if (!tid) s_inv = (scl*scl)/v;               // sc^2 / ||x||^2
    }

    // ===== S2: tile(9,8,7,6): bias9..6, E1(9,8), E1(7,6), O1(8,7)
#pragma unroll 1
    for (int it=0; it<4; ++it){
        const unsigned idx = (unsigned)tid | ((unsigned)it<<8);
        const unsigned pb  = swz((idx&63u) | ((idx>>6)<<10));
        ldtile<9,8,7,6>(S, pb, r);
        bias1<3>(r,Bt[9]); bias1<2>(r,Bt[8]); bias1<1>(r,Bt[7]); bias1<0>(r,Bt[6]);
        gate2<3,2>(r,Gt[2]); gate2<1,0>(r,Gt[3]); gate2<2,1>(r,Gt[9]);
        sttile<9,8,7,6>(S, pb, r);
    }
    __syncthreads();

    // ===== S3: tile(5,4,3,2): bias5..2, E1(5,4), E1(3,2), O1(4,3)
#pragma unroll 1
    for (int it=0; it<4; ++it){
        const unsigned idx = (unsigned)tid | ((unsigned)it<<8);
        const unsigned pb  = swz((idx&3u) | (((idx>>2)&7u)<<10) | (((idx>>5)&15u)<<6) | ((idx>>9)<<13));
        ldtile<5,4,3,2>(S, pb, r);
        bias1<3>(r,Bt[5]); bias1<2>(r,Bt[4]); bias1<1>(r,Bt[3]); bias1<0>(r,Bt[2]);
        gate2<3,2>(r,Gt[4]); gate2<1,0>(r,Gt[5]); gate2<2,1>(r,Gt[11]);
        sttile<5,4,3,2>(S, pb, r);
    }
    __syncthreads();

    // ===== S4: tile(3,2,1,0) contiguous, float4: bias1,0, E1(1,0), O1(2,1), E2(1,0)
#pragma unroll 1
    for (int it=0; it<4; ++it){
        const unsigned idx  = (unsigned)tid | ((unsigned)it<<8);
        const unsigned base = ((idx&3u)<<10) | (((idx>>2)&63u)<<4) | ((idx>>8)<<12);
        const unsigned pb   = swz(base);             // bits 0,1 of pb are 0
#pragma unroll
        for (int m=0;m<4;++m){
            float4 v = *(const float4*)(S + (pb ^ (unsigned)(m<<2)));
            r[4*m]=v.x; r[4*m+1]=v.y; r[4*m+2]=v.z; r[4*m+3]=v.w;
        }
        bias1<1>(r,Bt[1]); bias1<0>(r,Bt[0]);
        gate2<1,0>(r,Gt[6]); gate2<2,1>(r,Gt[12]); gate2<1,0>(r,Gt[19]);
#pragma unroll
        for (int m=0;m<4;++m)
            *(float4*)(S + (pb ^ (unsigned)(m<<2))) =
                make_float4(r[4*m],r[4*m+1],r[4*m+2],r[4*m+3]);
    }
    __syncthreads();

    // ===== S5: tile(11,10,9,8): O1(10,9), E2(11,10), E2(9,8), O2(10,9)
#pragma unroll 1
    for (int it=0; it<4; ++it){
        const unsigned idx = (unsigned)tid | ((unsigned)it<<8);
        const unsigned pb  = swz((idx&255u) | ((idx>>8)<<12));
        ldtile<11,10,9,8>(S, pb, r);
        gate2<2,1>(r,Gt[8]); gate2<3,2>(r,Gt[14]); gate2<1,0>(r,Gt[15]); gate2<2,1>(r,Gt[21]);
        sttile<11,10,9,8>(S, pb, r);
    }
    __syncthreads();

    // ===== S6: tile(12,11,6,5): O1(6,5), O2(12,11)
#pragma unroll 1
    for (int it=0; it<4; ++it){
        const unsigned idx = (unsigned)tid | ((unsigned)it<<8);
        const unsigned pb  = swz((idx&31u) | (((idx>>5)&15u)<<7) | ((idx>>9)<<13));
        ldtile<12,11,6,5>(S, pb, r);
        gate2<1,0>(r,Gt[10]); gate2<3,2>(r,Gt[20]);
        sttile<12,11,6,5>(S, pb, r);
    }
    __syncthreads();

    // ===== S7: tile(8,7,6,5): E2(7,6), O2(8,7)
#pragma unroll 1
    for (int it=0; it<4; ++it){
        const unsigned idx = (unsigned)tid | ((unsigned)it<<8);
        const unsigned pb  = swz((idx&31u) | ((idx>>5)<<9));
        ldtile<8,7,6,5>(S, pb, r);
        gate2<2,1>(r,Gt[16]); gate2<3,2>(r,Gt[22]);
        sttile<8,7,6,5>(S, pb, r);
    }
    __syncthreads();

    // ===== S8: tile(5,4,3,2): E2(5,4), E2(3,2), O2(4,3)
#pragma unroll 1
    for (int it=0; it<4; ++it){
        const unsigned idx = (unsigned)tid | ((unsigned)it<<8);
        const unsigned pb  = swz((idx&3u) | (((idx>>2)&7u)<<10) | (((idx>>5)&15u)<<6) | ((idx>>9)<<13));
        ldtile<5,4,3,2>(S, pb, r);
        gate2<3,2>(r,Gt[17]); gate2<1,0>(r,Gt[18]); gate2<2,1>(r,Gt[24]);
        sttile<5,4,3,2>(S, pb, r);
    }
    __syncthreads();

    // ===== S9: tile(6,5,2,1): O2(6,5), O2(2,1)   (2-way bank conflict, accepted)
#pragma unroll 1
    for (int it=0; it<4; ++it){
        const unsigned idx  = (unsigned)tid | ((unsigned)it<<8);
        const unsigned base = (idx&1u) | (((idx>>1)&1u)<<10) | (((idx>>2)&3u)<<3) | (((idx>>4)&1u)<<7)
                            | (((idx>>5)&3u)<<8) | (((idx>>7)&1u)<<11) | ((idx>>8)<<12);
        const unsigned pb   = swz(base);
        ldtile<6,5,2,1>(S, pb, r);
        gate2<3,2>(r,Gt[23]); gate2<1,0>(r,Gt[25]);
        sttile<6,5,2,1>(S, pb, r);
    }
    __syncthreads();

    // ---- epilogue: probs of last OUT_N states, scaled by sc^2/||x||^2 ----
    const float inv = s_inv;
    float* orow = out + (size_t)b*OUT_N;
    for (int j=tid; j<OUT_N; j+=BLK){
        float a = S[swz((unsigned)(DIM-OUT_N+j))];
        orow[j] = a*a*inv;
    }
}

extern "C" void kernel_launch(void* const* d_in, const int* in_sizes, int n_in,
                              void* d_out, int out_size)
{
    const float* input   = (const float*)d_in[0];   // (B,16384) f32
    const float* weights = (const float*)d_in[1];   // (2,13,2)  f32
    const float* bias    = (const float*)d_in[2];   // (14,)     f32
    float* out = (float*)d_out;                     // (B,1000)  f32

    const int B = in_sizes[0] / DIM;                // 512

    cudaFuncSetAttribute(qnn_kernel,
                         cudaFuncAttributeMaxDynamicSharedMemorySize,
                         DIM * (int)sizeof(float));

    qnn_kernel<<<B, BLK, DIM * sizeof(float)>>>(input, weights, bias, out);
}

// round 15
// speedup vs baseline: 2.2987x; 1.1096x over previous
#include <cuda_runtime.h>
#include <cstddef>

#define DIM   16384
#define OUT_N 1000
#define BLK   256

// bank bits 2-4 ^= addr bits 10-12; bits 0,1 intact (float2/float4-safe). Linear over GF(2).
__device__ __forceinline__ unsigned swz(unsigned a){ return a ^ (((a>>10)&7u)<<2); }

// Tangent-form fused CZ + RY(high PH) + RY(low PL); g=(t0,t1). Cosine scale deferred.
template<int PH,int PL>
__device__ __forceinline__ void gate2(float r[16], float2 g){
    const float t0 = g.x, t1 = g.y;
#pragma unroll
    for(int k=0;k<16;++k) if(!((k>>PH)&1) && !((k>>PL)&1)){
        const int k01=k|(1<<PL), k10=k|(1<<PH), k11=k10|(1<<PL);
        float y00 = fmaf(-t0, r[k10],  r[k]);
        float y10 = fmaf( t0, r[k],    r[k10]);
        float y01 = fmaf( t0, r[k11],  r[k01]);   // a01 - t0*(-a11)  (CZ fold)
        float y11 = fmaf( t0, r[k01], -r[k11]);   // -a11 + t0*a01
        r[k]   = fmaf(-t1, y01, y00);
        r[k01] = fmaf( t1, y00, y01);
        r[k10] = fmaf(-t1, y11, y10);
        r[k11] = fmaf( t1, y10, y11);
    }
}
template<int P>
__device__ __forceinline__ void bias1(float r[16], float t){
#pragma unroll
    for(int k=0;k<16;++k) if(!((k>>P)&1)){
        const int k1 = k|(1<<P);
        float y0 = fmaf(-t, r[k1], r[k]);
        r[k1]    = fmaf( t, r[k],  r[k1]);
        r[k]     = y0;
    }
}

// 64-bit tile ld/st: spectator = amp bit 0 (pb even). Two 16-amp register tiles.
template<int B3,int B2,int B1,int B0>
__device__ __forceinline__ void ld2(const float* __restrict__ S, unsigned pb,
                                    float a[16], float b[16]){
#pragma unroll
    for(int k=0;k<16;++k){
        const unsigned off = swz((unsigned)((((k>>3)&1)<<B3)|(((k>>2)&1)<<B2)|(((k>>1)&1)<<B1)|((k&1)<<B0)));
        float2 v = *(const float2*)(S + (pb ^ off));
        a[k] = v.x; b[k] = v.y;
    }
}
template<int B3,int B2,int B1,int B0>
__device__ __forceinline__ void st2(float* __restrict__ S, unsigned pb,
                                    const float a[16], const float b[16]){
#pragma unroll
    for(int k=0;k<16;++k){
        const unsigned off = swz((unsigned)((((k>>3)&1)<<B3)|(((k>>2)&1)<<B2)|(((k>>1)&1)<<B1)|((k&1)<<B0)));
        *(float2*)(S + (pb ^ off)) = make_float2(a[k], b[k]);
    }
}

__global__ __launch_bounds__(BLK, 3)
void qnn_kernel(const float* __restrict__ input,
                const float* __restrict__ weights,   // (2,13,2)
                const float* __restrict__ bias,      // (14,)
                float* __restrict__ out)             // (B,1000)
{
    extern __shared__ float S[];                     // DIM floats, swizzled layout
    __shared__ float2 Gt[26];                        // (t0,t1) per fused gate
    __shared__ float  Bt[14];                        // bias tan, by BIT position
    __shared__ float  Cg[26], Cb[14];                // deferred cosines
    __shared__ float  warpsum[BLK/32];
    __shared__ float  s_inv;

    const int tid = threadIdx.x;
    const int b   = blockIdx.x;

    // id 0-6: L1 even (i=2*id) -> bits(13-i,12-i); 7-12: L1 odd; 13-19: L2 even; 20-25: L2 odd
    if (tid < 26) {
        int l, i;
        if (tid < 7)       { l=0; i=2*tid; }
        else if (tid < 13) { l=0; i=2*(tid-7)+1; }
        else if (tid < 20) { l=1; i=2*(tid-13); }
        else               { l=1; i=2*(tid-20)+1; }
        float c0,s0,c1,s1;
        sincosf(0.5f*weights[l*26+i*2+0], &s0, &c0);
        sincosf(0.5f*weights[l*26+i*2+1], &s1, &c1);
        Gt[tid] = make_float2(s0/c0, s1/c1);
        Cg[tid] = c0*c1;
    }
    if (tid < 14) {                                  // bit w holds qubit 13-w
        float c,s; sincosf(0.5f*bias[13-tid], &s, &c);
        Bt[tid] = s/c; Cb[tid] = c;
    }
    __syncthreads();

    // warp 0: product of all 66 cosines
    float scl = 1.f;
    if (tid < 32) {
        if (tid < 26) scl *= Cg[tid];
        if (tid < 14) scl *= Cb[tid];
#pragma unroll
        for (int o=16;o;o>>=1) scl *= __shfl_xor_sync(~0u, scl, o);
    }

    float rA[16], rB[16];
    float acc0 = 0.f, acc1 = 0.f;

    // ===== S1 (gmem -> regs -> smem): tile(13,12,11,10), spec bit 0, base idx<<1
    //   bias13..10, E1(13,12), E1(11,10), O1(12,11), E2(13,12)
    const float* row = input + (size_t)b * DIM;
#pragma unroll 1
    for (int it=0; it<2; ++it){
        const unsigned idx = (unsigned)tid | ((unsigned)it<<8);   // [0,512)
        const unsigned base = idx << 1;
#pragma unroll
        for (int k=0;k<16;++k){
            float2 v = *(const float2*)(row + (base | ((unsigned)k<<10)));
            acc0 = fmaf(v.x,v.x,acc0); acc1 = fmaf(v.y,v.y,acc1);
            rA[k] = v.x; rB[k] = v.y;
        }
        bias1<3>(rA,Bt[13]); bias1<3>(rB,Bt[13]);
        bias1<2>(rA,Bt[12]); bias1<2>(rB,Bt[12]);
        bias1<1>(rA,Bt[11]); bias1<1>(rB,Bt[11]);
        bias1<0>(rA,Bt[10]); bias1<0>(rB,Bt[10]);
        gate2<3,2>(rA,Gt[0]);  gate2<3,2>(rB,Gt[0]);
        gate2<1,0>(rA,Gt[1]);  gate2<1,0>(rB,Gt[1]);
        gate2<2,1>(rA,Gt[7]);  gate2<2,1>(rB,Gt[7]);
        gate2<3,2>(rA,Gt[13]); gate2<3,2>(rB,Gt[13]);
        st2<13,12,11,10>(S, swz(base), rA, rB);
    }
    {
        float acc = acc0 + acc1;
#pragma unroll
        for (int o=16;o;o>>=1) acc += __shfl_xor_sync(~0u, acc, o);
        if ((tid&31)==0) warpsum[tid>>5] = acc;
    }
    __syncthreads();                                 // orders S1 stores before S2 loads
    if (tid < BLK/32){
        float v = warpsum[tid];
#pragma unroll
        for (int o=(BLK/32)/2;o;o>>=1) v += __shfl_xor_sync(0xffu, v, o);
        if (!tid) s_inv = (scl*scl)/v;               // sc^2 / ||x||^2
    }

    // ===== S2: tile(9,8,7,6), spec 0, base {1-5,10-13}: bias9..6, E1(9,8), E1(7,6), O1(8,7)
#pragma unroll 1
    for (int it=0; it<2; ++it){
        const unsigned idx = (unsigned)tid | ((unsigned)it<<8);
        const unsigned pb  = swz(((idx&31u)<<1) | ((idx>>5)<<10));
        ld2<9,8,7,6>(S, pb, rA, rB);
        bias1<3>(rA,Bt[9]); bias1<3>(rB,Bt[9]);
        bias1<2>(rA,Bt[8]); bias1<2>(rB,Bt[8]);
        bias1<1>(rA,Bt[7]); bias1<1>(rB,Bt[7]);
        bias1<0>(rA,Bt[6]); bias1<0>(rB,Bt[6]);
        gate2<3,2>(rA,Gt[2]); gate2<3,2>(rB,Gt[2]);
        gate2<1,0>(rA,Gt[3]); gate2<1,0>(rB,Gt[3]);
        gate2<2,1>(rA,Gt[9]); gate2<2,1>(rB,Gt[9]);
        st2<9,8,7,6>(S, pb, rA, rB);
    }
    __syncthreads();

    // ===== S3: tile(5,4,3,2), spec 0, base {1,6-9,10-13}: bias5..2, E1(5,4), E1(3,2), O1(4,3)
#pragma unroll 1
    for (int it=0; it<2; ++it){
        const unsigned idx = (unsigned)tid | ((unsigned)it<<8);
        const unsigned pb  = swz(((idx&1u)<<1) | (((idx>>1)&7u)<<10)
                               | (((idx>>4)&15u)<<6) | ((idx>>8)<<13));
        ld2<5,4,3,2>(S, pb, rA, rB);
        bias1<3>(rA,Bt[5]); bias1<3>(rB,Bt[5]);
        bias1<2>(rA,Bt[4]); bias1<2>(rB,Bt[4]);
        bias1<1>(rA,Bt[3]); bias1<1>(rB,Bt[3]);
        bias1<0>(rA,Bt[2]); bias1<0>(rB,Bt[2]);
        gate2<3,2>(rA,Gt[4]);  gate2<3,2>(rB,Gt[4]);
        gate2<1,0>(rA,Gt[5]);  gate2<1,0>(rB,Gt[5]);
        gate2<2,1>(rA,Gt[11]); gate2<2,1>(rB,Gt[11]);
        st2<5,4,3,2>(S, pb, rA, rB);
    }
    __syncthreads();

    // ===== S4: tile(3,2,1,0) contiguous (float4), spec bit 4, base {5-13}
    //   bias1,0, E1(1,0), O1(2,1), E2(1,0)
#pragma unroll 1
    for (int it=0; it<2; ++it){
        const unsigned idx  = (unsigned)tid | ((unsigned)it<<8);
        const unsigned base = ((idx&7u)<<10) | (((idx>>3)&31u)<<5) | ((idx>>8)<<13);
        const unsigned pb   = swz(base);             // bits 0,1 of pb are 0
#pragma unroll
        for (int m=0;m<4;++m){
            float4 v = *(const float4*)(S + (pb ^ (unsigned)(m<<2)));
            rA[4*m]=v.x; rA[4*m+1]=v.y; rA[4*m+2]=v.z; rA[4*m+3]=v.w;
            float4 w = *(const float4*)(S + (pb ^ (unsigned)((m<<2)|16)));
            rB[4*m]=w.x; rB[4*m+1]=w.y; rB[4*m+2]=w.z; rB[4*m+3]=w.w;
        }
        bias1<1>(rA,Bt[1]); bias1<1>(rB,Bt[1]);
        bias1<0>(rA,Bt[0]); bias1<0>(rB,Bt[0]);
        gate2<1,0>(rA,Gt[6]);  gate2<1,0>(rB,Gt[6]);
        gate2<2,1>(rA,Gt[12]); gate2<2,1>(rB,Gt[12]);
        gate2<1,0>(rA,Gt[19]); gate2<1,0>(rB,Gt[19]);
#pragma unroll
        for (int m=0;m<4;++m){
            *(float4*)(S + (pb ^ (unsigned)(m<<2))) =
                make_float4(rA[4*m],rA[4*m+1],rA[4*m+2],rA[4*m+3]);
            *(float4*)(S + (pb ^ (unsigned)((m<<2)|16))) =
                make_float4(rB[4*m],rB[4*m+1],rB[4*m+2],rB[4*m+3]);
        }
    }
    __syncthreads();

    // ===== S5: tile(11,10,9,8), spec 0, base {1-7,12,13}: O1(10,9), E2(11,10), E2(9,8), O2(10,9)
#pragma unroll 1
    for (int it=0; it<2; ++it){
        const unsigned idx = (unsigned)tid | ((unsigned)it<<8);
        const unsigned pb  = swz(((idx&127u)<<1) | ((idx>>7)<<12));
        ld2<11,10,9,8>(S, pb, rA, rB);
        gate2<2,1>(rA,Gt[8]);  gate2<2,1>(rB,Gt[8]);
        gate2<3,2>(rA,Gt[14]); gate2<3,2>(rB,Gt[14]);
        gate2<1,0>(rA,Gt[15]); gate2<1,0>(rB,Gt[15]);
        gate2<2,1>(rA,Gt[21]); gate2<2,1>(rB,Gt[21]);
        st2<11,10,9,8>(S, pb, rA, rB);
    }
    __syncthreads();

    // ===== S6: tile(12,11,6,5), spec 0, base {1-4,7-10,13}: O1(6,5), O2(12,11)
#pragma unroll 1
    for (int it=0; it<2; ++it){
        const unsigned idx = (unsigned)tid | ((unsigned)it<<8);
        const unsigned pb  = swz(((idx&15u)<<1) | (((idx>>4)&15u)<<7) | ((idx>>8)<<13));
        ld2<12,11,6,5>(S, pb, rA, rB);
        gate2<1,0>(rA,Gt[10]); gate2<1,0>(rB,Gt[10]);
        gate2<3,2>(rA,Gt[20]); gate2<3,2>(rB,Gt[20]);
        st2<12,11,6,5>(S, pb, rA, rB);
    }
    __syncthreads();

    // ===== S7: tile(8,7,6,5), spec 0, base {1-4,9-13}: E2(7,6), O2(8,7)
#pragma unroll 1
    for (int it=0; it<2; ++it){
        const unsigned idx = (unsigned)tid | ((unsigned)it<<8);
        const unsigned pb  = swz(((idx&15u)<<1) | ((idx>>4)<<9));
        ld2<8,7,6,5>(S, pb, rA, rB);
        gate2<2,1>(rA,Gt[16]); gate2<2,1>(rB,Gt[16]);
        gate2<3,2>(rA,Gt[22]); gate2<3,2>(rB,Gt[22]);
        st2<8,7,6,5>(S, pb, rA, rB);
    }
    __syncthreads();

    // ===== S8: tile(5,4,3,2), spec 0 (same base map as S3): E2(5,4), E2(3,2), O2(4,3)
#pragma unroll 1
    for (int it=0; it<2; ++it){
        const unsigned idx = (unsigned)tid | ((unsigned)it<<8);
        const unsigned pb  = swz(((idx&1u)<<1) | (((idx>>1)&7u)<<10)
                               | (((idx>>4)&15u)<<6) | ((idx>>8)<<13));
        ld2<5,4,3,2>(S, pb, rA, rB);
        gate2<3,2>(rA,Gt[17]); gate2<3,2>(rB,Gt[17]);
        gate2<1,0>(rA,Gt[18]); gate2<1,0>(rB,Gt[18]);
        gate2<2,1>(rA,Gt[24]); gate2<2,1>(rB,Gt[24]);
        st2<5,4,3,2>(S, pb, rA, rB);
    }
    __syncthreads();

    // ===== S9: tile(6,5,2,1), spec 0, base {3,4,7,8,9,10,11,12,13}: O2(6,5), O2(2,1)
    //   (2-way bank conflict inherent; same degree as before)
#pragma unroll 1
    for (int it=0; it<2; ++it){
        const unsigned idx  = (unsigned)tid | ((unsigned)it<<8);
        const unsigned base = ((idx&1u)<<3) | (((idx>>1)&1u)<<4)
                            | (((idx>>2)&1u)<<10) | (((idx>>3)&1u)<<11)
                            | (((idx>>4)&7u)<<7) | ((idx>>7)<<12);
        const unsigned pb   = swz(base);
        ld2<6,5,2,1>(S, pb, rA, rB);
        gate2<3,2>(rA,Gt[23]); gate2<3,2>(rB,Gt[23]);
        gate2<1,0>(rA,Gt[25]); gate2<1,0>(rB,Gt[25]);
        st2<6,5,2,1>(S, pb, rA, rB);
    }
    __syncthreads();

    // ---- epilogue: probs of last OUT_N states, scaled by sc^2/||x||^2 ----
    const float inv = s_inv;
    float* orow = out + (size_t)b*OUT_N;
    for (int j=tid; j<OUT_N; j+=BLK){
        float a = S[swz((unsigned)(DIM-OUT_N+j))];
        orow[j] = a*a*inv;
    }
}

extern "C" void kernel_launch(void* const* d_in, const int* in_sizes, int n_in,
                              void* d_out, int out_size)
{
    const float* input   = (const float*)d_in[0];   // (B,16384) f32
    const float* weights = (const float*)d_in[1];   // (2,13,2)  f32
    const float* bias    = (const float*)d_in[2];   // (14,)     f32
    float* out = (float*)d_out;                     // (B,1000)  f32

    const int B = in_sizes[0] / DIM;                // 512

    cudaFuncSetAttribute(qnn_kernel,
                         cudaFuncAttributeMaxDynamicSharedMemorySize,
                         DIM * (int)sizeof(float));

    qnn_kernel<<<B, BLK, DIM * sizeof(float)>>>(input, weights, bias, out);
}